// round 4
// baseline (speedup 1.0000x reference)
#include <cuda_runtime.h>
#include <cuda_fp16.h>

#define Bn 4
#define Cn 32
#define Hn 512
#define Wn 512
#define HWn (Hn * Wn)
#define PSTRIP 64

// Single reused NHWC fp16 scratch (one batch): [H][W][C] = 16 MB. Stays L2-resident.
__device__ __half g_xt[(size_t)Hn * Wn * Cn];

// ---------------------------------------------------------------------------
// Pass 1 (per batch): NCHW fp32 -> NHWC fp16. Block = (32 c) x (32 w) at (h).
// ---------------------------------------------------------------------------
__global__ __launch_bounds__(256) void transpose_kernel(const float* __restrict__ xb)
{
    __shared__ float tile[32][33];
    const int w0 = blockIdx.x * 32;
    const int h  = blockIdx.y;
    const int tid = threadIdx.x;

    // load: thread (c = tid>>3, wq = tid&7) reads float4 at w0 + wq*4
    const int c  = tid >> 3;
    const int wq = tid & 7;
    const float4 v = __ldg((const float4*)(
        xb + (size_t)c * HWn + h * Wn + w0 + wq * 4));
    tile[wq * 4 + 0][c] = v.x;
    tile[wq * 4 + 1][c] = v.y;
    tile[wq * 4 + 2][c] = v.z;
    tile[wq * 4 + 3][c] = v.w;
    __syncthreads();

    // store: thread (pix = tid>>3, part = tid&7) writes channels part*4..+3
    const int pix  = tid >> 3;
    const int part = tid & 7;
    const __half2 h0 = __floats2half2_rn(tile[pix][part * 4 + 0],
                                         tile[pix][part * 4 + 1]);
    const __half2 h1 = __floats2half2_rn(tile[pix][part * 4 + 2],
                                         tile[pix][part * 4 + 3]);
    uint2 u;
    u.x = *(const unsigned int*)&h0;
    u.y = *(const unsigned int*)&h1;
    *(uint2*)((char*)(g_xt + ((size_t)(h * Wn) + w0 + pix) * Cn) + part * 8) = u;
}

// ---------------------------------------------------------------------------
// Pass 2 (per batch): params once in smem, fp16 NHWC gathers (4 lanes x 16B
// per pixel), smem transpose, float4 residual-add + NCHW store.
// Block = 64-pixel w-strip at fixed h.
// ---------------------------------------------------------------------------
__global__ __launch_bounds__(256) void warp_gather_kernel(
    const float* __restrict__ flowb,
    const float* __restrict__ residualb,
    float* __restrict__ outb)
{
    __shared__ float s_wt[4][PSTRIP];   // tl,tr,bl,br weights
    __shared__ int   s_of[4][PSTRIP];   // tl,tr,bl,br pixel offsets
    __shared__ float sres[PSTRIP * 33]; // [pixel][channel]

    const int w0  = blockIdx.x * PSTRIP;
    const int h   = blockIdx.y;
    const int tid = threadIdx.x;

    // ---- phase 0: 64 threads compute per-pixel sampling params ----
    if (tid < PSTRIP) {
        const int w = w0 + tid;
        const int pix = h * Wn + w;
        const float fx = __ldg(flowb + pix);
        const float fy = __ldg(flowb + HWn + pix);

        float gx = (w + 0.5f) * (2.0f / Wn) - 1.0f + fx;
        float gy = (h + 0.5f) * (2.0f / Hn) - 1.0f + fy;

        // circular wrap on x: mod(gx+1, 2) - 1
        float t = gx + 1.0f;
        t = t - floorf(t * 0.5f) * 2.0f;
        gx = t - 1.0f;

        const float rx = (gx + 1.0f) * (Wn * 0.5f) - 0.5f;
        const float ry = (gy + 1.0f) * (Hn * 0.5f) - 0.5f;

        const float x0f = floorf(rx);
        const float y0f = floorf(ry);
        const float dx = rx - x0f;
        const float dy = ry - y0f;

        const int ix0 = (int)x0f, iy0 = (int)y0f;
        const int ix1 = ix0 + 1,  iy1 = iy0 + 1;

        const float vx0 = (ix0 >= 0 && ix0 < Wn) ? 1.0f : 0.0f;
        const float vx1 = (ix1 >= 0 && ix1 < Wn) ? 1.0f : 0.0f;
        const float vy0 = (iy0 >= 0 && iy0 < Hn) ? 1.0f : 0.0f;
        const float vy1 = (iy1 >= 0 && iy1 < Hn) ? 1.0f : 0.0f;

        s_wt[0][tid] = (1.0f - dx) * (1.0f - dy) * vx0 * vy0;
        s_wt[1][tid] = dx * (1.0f - dy) * vx1 * vy0;
        s_wt[2][tid] = (1.0f - dx) * dy * vx0 * vy1;
        s_wt[3][tid] = dx * dy * vx1 * vy1;

        const int cx0 = min(max(ix0, 0), Wn - 1);
        const int cx1 = min(max(ix1, 0), Wn - 1);
        const int cy0 = min(max(iy0, 0), Hn - 1);
        const int cy1 = min(max(iy1, 0), Hn - 1);
        s_of[0][tid] = cy0 * Wn + cx0;
        s_of[1][tid] = cy0 * Wn + cx1;
        s_of[2][tid] = cy1 * Wn + cx0;
        s_of[3][tid] = cy1 * Wn + cx1;
    }
    __syncthreads();

    // ---- phase 1: gather. thread = (pixel i, 8-channel group q) ----
    {
        const int i = tid >> 2;     // 0..63
        const int q = tid & 3;      // 0..3 (channels q*8 .. q*8+7)
        const __half* xb = g_xt + q * 8;

        float r[8];
#pragma unroll
        for (int k = 0; k < 8; ++k) r[k] = 0.0f;

#pragma unroll
        for (int cnr = 0; cnr < 4; ++cnr) {
            const float wt = s_wt[cnr][i];
            const uint4 ld = __ldg((const uint4*)(xb + (size_t)s_of[cnr][i] * Cn));
            const unsigned int uu[4] = {ld.x, ld.y, ld.z, ld.w};
#pragma unroll
            for (int j = 0; j < 4; ++j) {
                const float2 f = __half22float2(*(const __half2*)&uu[j]);
                r[j * 2 + 0] += wt * f.x;
                r[j * 2 + 1] += wt * f.y;
            }
        }

        float* s = sres + i * 33 + q * 8;
#pragma unroll
        for (int k = 0; k < 8; ++k) s[k] = r[k];
    }
    __syncthreads();

    // ---- phase 2: float4 residual-add + coalesced NCHW store ----
    {
        const int wq = tid & 15;    // w quad: pixels wq*4 .. wq*4+3
        const int cl = tid >> 4;    // 0..15
        const size_t base = (size_t)(h * Wn) + w0 + wq * 4;
#pragma unroll
        for (int cc = 0; cc < 32; cc += 16) {
            const int c = cc + cl;
            const size_t o = base + (size_t)c * HWn;
            float4 rr = __ldg((const float4*)(residualb + o));
            rr.x += sres[(wq * 4 + 0) * 33 + c];
            rr.y += sres[(wq * 4 + 1) * 33 + c];
            rr.z += sres[(wq * 4 + 2) * 33 + c];
            rr.w += sres[(wq * 4 + 3) * 33 + c];
            *(float4*)(outb + o) = rr;
        }
    }
}

extern "C" void kernel_launch(void* const* d_in, const int* in_sizes, int n_in,
                              void* d_out, int out_size)
{
    const float* x        = (const float*)d_in[0];
    const float* flow     = (const float*)d_in[1];
    const float* residual = (const float*)d_in[2];
    float*       out      = (float*)d_out;

    dim3 gridT(Wn / 32, Hn);
    dim3 gridG(Wn / PSTRIP, Hn);
    for (int b = 0; b < Bn; ++b) {
        transpose_kernel<<<gridT, 256>>>(x + (size_t)b * Cn * HWn);
        warp_gather_kernel<<<gridG, 256>>>(flow + (size_t)b * 2 * HWn,
                                           residual + (size_t)b * Cn * HWn,
                                           out + (size_t)b * Cn * HWn);
    }
}

// round 5
// speedup vs baseline: 1.0536x; 1.0536x over previous
#include <cuda_runtime.h>
#include <cuda_fp16.h>

#define Bn 4
#define Cn 32
#define Hn 512
#define Wn 512
#define HWn (Hn * Wn)
#define PSTRIP 64

// Two 16MB NHWC fp16 scratch buffers (double-buffered across batches; L2-resident)
__device__ __half g_xt[2][(size_t)HWn * Cn];

// ---------------------------------------------------------------------------
// Transpose one 64w x 32c tile of NCHW fp32 -> NHWC fp16 at row h.
// ---------------------------------------------------------------------------
__device__ __forceinline__ void transpose_tile(const float* __restrict__ xb,
                                               __half* __restrict__ dst,
                                               int w0, int h, int tid)
{
    __shared__ float tile[64][33];
#pragma unroll
    for (int iter = 0; iter < 2; ++iter) {
        const int c  = iter * 16 + (tid >> 4);
        const int wq = tid & 15;
        const float4 v = __ldg((const float4*)(
            xb + (size_t)c * HWn + h * Wn + w0 + wq * 4));
        tile[wq * 4 + 0][c] = v.x;
        tile[wq * 4 + 1][c] = v.y;
        tile[wq * 4 + 2][c] = v.z;
        tile[wq * 4 + 3][c] = v.w;
    }
    __syncthreads();

    // store: thread (pix = tid>>2, part = tid&3) -> 8 channels -> one uint4
    const int pix  = tid >> 2;
    const int part = tid & 3;
    __half2 hh[4];
#pragma unroll
    for (int j = 0; j < 4; ++j)
        hh[j] = __floats2half2_rn(tile[pix][part * 8 + j * 2],
                                  tile[pix][part * 8 + j * 2 + 1]);
    uint4 u;
    u.x = *(const unsigned int*)&hh[0];
    u.y = *(const unsigned int*)&hh[1];
    u.z = *(const unsigned int*)&hh[2];
    u.w = *(const unsigned int*)&hh[3];
    *(uint4*)((char*)(dst + ((size_t)(h * Wn) + w0 + pix) * Cn) + part * 16) = u;
}

// ---------------------------------------------------------------------------
// Gather one 64-pixel w-strip at row h from NHWC fp16 src; residual-add +
// coalesced NCHW fp32 store.
// ---------------------------------------------------------------------------
__device__ __forceinline__ void gather_strip(const __half* __restrict__ src,
                                             const float* __restrict__ flowb,
                                             const float* __restrict__ residualb,
                                             float* __restrict__ outb,
                                             int w0, int h, int tid)
{
    __shared__ float s_wt[4][PSTRIP];
    __shared__ int   s_of[4][PSTRIP];
    __shared__ float sres[PSTRIP * 33];

    // ---- phase 0: per-pixel sampling params ----
    if (tid < PSTRIP) {
        const int w = w0 + tid;
        const int pix = h * Wn + w;
        const float fx = __ldg(flowb + pix);
        const float fy = __ldg(flowb + HWn + pix);

        float gx = (w + 0.5f) * (2.0f / Wn) - 1.0f + fx;
        float gy = (h + 0.5f) * (2.0f / Hn) - 1.0f + fy;

        // circular wrap on x: mod(gx+1, 2) - 1
        float t = gx + 1.0f;
        t = t - floorf(t * 0.5f) * 2.0f;
        gx = t - 1.0f;

        const float rx = (gx + 1.0f) * (Wn * 0.5f) - 0.5f;
        const float ry = (gy + 1.0f) * (Hn * 0.5f) - 0.5f;

        const float x0f = floorf(rx);
        const float y0f = floorf(ry);
        const float dx = rx - x0f;
        const float dy = ry - y0f;

        const int ix0 = (int)x0f, iy0 = (int)y0f;
        const int ix1 = ix0 + 1,  iy1 = iy0 + 1;

        const float vx0 = (ix0 >= 0 && ix0 < Wn) ? 1.0f : 0.0f;
        const float vx1 = (ix1 >= 0 && ix1 < Wn) ? 1.0f : 0.0f;
        const float vy0 = (iy0 >= 0 && iy0 < Hn) ? 1.0f : 0.0f;
        const float vy1 = (iy1 >= 0 && iy1 < Hn) ? 1.0f : 0.0f;

        s_wt[0][tid] = (1.0f - dx) * (1.0f - dy) * vx0 * vy0;
        s_wt[1][tid] = dx * (1.0f - dy) * vx1 * vy0;
        s_wt[2][tid] = (1.0f - dx) * dy * vx0 * vy1;
        s_wt[3][tid] = dx * dy * vx1 * vy1;

        const int cx0 = min(max(ix0, 0), Wn - 1);
        const int cx1 = min(max(ix1, 0), Wn - 1);
        const int cy0 = min(max(iy0, 0), Hn - 1);
        const int cy1 = min(max(iy1, 0), Hn - 1);
        s_of[0][tid] = cy0 * Wn + cx0;
        s_of[1][tid] = cy0 * Wn + cx1;
        s_of[2][tid] = cy1 * Wn + cx0;
        s_of[3][tid] = cy1 * Wn + cx1;
    }
    __syncthreads();

    // ---- phase 1: gather. thread = (pixel i, 8-channel group q) ----
    {
        const int i = tid >> 2;
        const int q = tid & 3;
        const __half* xb = src + q * 8;

        float r[8];
#pragma unroll
        for (int k = 0; k < 8; ++k) r[k] = 0.0f;

#pragma unroll
        for (int cnr = 0; cnr < 4; ++cnr) {
            const float wt = s_wt[cnr][i];
            const uint4 ld = __ldg((const uint4*)(xb + (size_t)s_of[cnr][i] * Cn));
            const unsigned int uu[4] = {ld.x, ld.y, ld.z, ld.w};
#pragma unroll
            for (int j = 0; j < 4; ++j) {
                const float2 f = __half22float2(*(const __half2*)&uu[j]);
                r[j * 2 + 0] += wt * f.x;
                r[j * 2 + 1] += wt * f.y;
            }
        }

        float* s = sres + i * 33 + q * 8;
#pragma unroll
        for (int k = 0; k < 8; ++k) s[k] = r[k];
    }
    __syncthreads();

    // ---- phase 2: float4 residual-add + coalesced NCHW store ----
    {
        const int wq = tid & 15;
        const int cl = tid >> 4;
        const size_t base = (size_t)(h * Wn) + w0 + wq * 4;
#pragma unroll
        for (int cc = 0; cc < 32; cc += 16) {
            const int c = cc + cl;
            const size_t o = base + (size_t)c * HWn;
            float4 rr = __ldg((const float4*)(residualb + o));
            rr.x += sres[(wq * 4 + 0) * 33 + c];
            rr.y += sres[(wq * 4 + 1) * 33 + c];
            rr.z += sres[(wq * 4 + 2) * 33 + c];
            rr.w += sres[(wq * 4 + 3) * 33 + c];
            *(float4*)(outb + o) = rr;
        }
    }
}

// ---------------------------------------------------------------------------
// Kernels
// ---------------------------------------------------------------------------
__global__ __launch_bounds__(256) void transpose_kernel(
    const float* __restrict__ xb, int dstsel)
{
    transpose_tile(xb, g_xt[dstsel], blockIdx.x * 64, blockIdx.y, threadIdx.x);
}

__global__ __launch_bounds__(256) void gather_kernel(
    const float* __restrict__ flowb, const float* __restrict__ residualb,
    float* __restrict__ outb, int srcsel)
{
    gather_strip(g_xt[srcsel], flowb, residualb, outb,
                 blockIdx.x * PSTRIP, blockIdx.y, threadIdx.x);
}

// Fused: gather(batch b, buffer gsel) interleaved with transpose(batch b+1 -> gsel^1)
__global__ __launch_bounds__(256) void fused_kernel(
    const float* __restrict__ xnext,
    const float* __restrict__ flowb, const float* __restrict__ residualb,
    float* __restrict__ outb, int gsel)
{
    const int bx = blockIdx.x >> 1;
    if (blockIdx.x & 1)
        transpose_tile(xnext, g_xt[gsel ^ 1], bx * 64, blockIdx.y, threadIdx.x);
    else
        gather_strip(g_xt[gsel], flowb, residualb, outb,
                     bx * PSTRIP, blockIdx.y, threadIdx.x);
}

extern "C" void kernel_launch(void* const* d_in, const int* in_sizes, int n_in,
                              void* d_out, int out_size)
{
    const float* x        = (const float*)d_in[0];
    const float* flow     = (const float*)d_in[1];
    const float* residual = (const float*)d_in[2];
    float*       out      = (float*)d_out;

    dim3 gridT(Wn / 64, Hn);
    dim3 gridG(Wn / PSTRIP, Hn);
    dim3 gridF(2 * (Wn / PSTRIP), Hn);

    // pipeline: T(0), [G(b) || T(b+1)] for b=0..2, G(3)
    transpose_kernel<<<gridT, 256>>>(x, 0);
    for (int b = 0; b < Bn - 1; ++b) {
        fused_kernel<<<gridF, 256>>>(x + (size_t)(b + 1) * Cn * HWn,
                                     flow + (size_t)b * 2 * HWn,
                                     residual + (size_t)b * Cn * HWn,
                                     out + (size_t)b * Cn * HWn,
                                     b & 1);
    }
    gather_kernel<<<gridG, 256>>>(flow + (size_t)(Bn - 1) * 2 * HWn,
                                  residual + (size_t)(Bn - 1) * Cn * HWn,
                                  out + (size_t)(Bn - 1) * Cn * HWn,
                                  (Bn - 1) & 1);
}